// round 11
// baseline (speedup 1.0000x reference)
#include <cuda_runtime.h>
#include <math.h>
#include <stdint.h>

// ---------------- problem constants ----------------
#define B_EVT   100000
#define N_NODES 500000
#define MEM_D   500
#define MSG_D   100
#define TIME_D  100
#define EDGE_F  101
#define RAW_D   701
#define RAW_P   704          // tf32 raw row stride
#define ACT_P   352          // tf32 act row stride
#define KGRU    608          // [msg(100)|pad4|h(500)|pad4]
#define KB      104          // msg|h boundary (mult of 8)
#define H_P     512          // fp32 h row stride
#define W1_P    384          // w1t col pitch
#define W2_P    128
#define SLAB    512          // wstk per-gate col pitch
#define WSTK_P  1536         // 3*SLAB
#define MBLK    782          // ceil(100000/128)

// ---------------- static scratch ----------------
__device__ __align__(16) int      g_winner[N_NODES];
__device__ __align__(16) uint32_t g_rawt[(size_t)B_EVT * RAW_P];  // tf32 [h|edge|tenc|0]
__device__ __align__(16) uint32_t g_act [(size_t)B_EVT * ACT_P];  // tf32 relu(raw@W1+b1)
__device__ __align__(16) uint32_t g_x   [(size_t)B_EVT * KGRU];   // tf32 [msg|0|h|0]
__device__ __align__(16) float    g_h   [(size_t)B_EVT * H_P];    // fp32 h (epilogue)
__device__ __align__(16) uint32_t g_w1t [(size_t)RAW_P * W1_P];
__device__ __align__(16) uint32_t g_w2t [(size_t)ACT_P * W2_P];
__device__ __align__(16) uint32_t g_wstk[(size_t)KGRU * WSTK_P];

__device__ __forceinline__ float sigmoidf_(float x) { return 1.f / (1.f + expf(-x)); }
__device__ __forceinline__ uint32_t f2tf32(float x) {
    uint32_t r; asm("cvt.rna.tf32.f32 %0, %1;" : "=r"(r) : "f"(x)); return r;
}
__device__ __forceinline__ void mma8(float c[4], const uint32_t a[4], const uint32_t b[2]) {
    asm volatile(
        "mma.sync.aligned.m16n8k8.row.col.f32.tf32.tf32.f32 "
        "{%0,%1,%2,%3},{%4,%5,%6,%7},{%8,%9},{%0,%1,%2,%3};"
        : "+f"(c[0]), "+f"(c[1]), "+f"(c[2]), "+f"(c[3])
        : "r"(a[0]), "r"(a[1]), "r"(a[2]), "r"(a[3]), "r"(b[0]), "r"(b[1]));
}
__device__ __forceinline__ void cpa16(uint32_t dst, const void* src, int nbytes) {
    asm volatile("cp.async.cg.shared.global [%0], [%1], 16, %2;"
                 :: "r"(dst), "l"(src), "r"(nbytes));
}
#define CPA_COMMIT() asm volatile("cp.async.commit_group;")
#define CPA_WAIT1()  asm volatile("cp.async.wait_group 1;")
#define CPA_WAIT2()  asm volatile("cp.async.wait_group 2;")

// ---------------- winner: last event index per node ----------------
__global__ void k_winner(const int* __restrict__ node_ids) {
    int e = blockIdx.x * blockDim.x + threadIdx.x;
    if (e < B_EVT) atomicMax(&g_winner[node_ids[e]], e);
}

// ---------------- weight packing (tf32, zero-padded) ----------------
__global__ void k_prep_w1(const float* __restrict__ W1) {
    int i = blockIdx.x * blockDim.x + threadIdx.x;
    if (i >= RAW_P * W1_P) return;
    int k = i / W1_P, n = i - k * W1_P;
    float v = (k < RAW_D && n < 350) ? W1[k * 350 + n] : 0.f;
    g_w1t[i] = f2tf32(v);
}
__global__ void k_prep_w2(const float* __restrict__ W2) {
    int i = blockIdx.x * blockDim.x + threadIdx.x;
    if (i >= ACT_P * W2_P) return;
    int k = i / W2_P, n = i - k * W2_P;
    float v = (k < 350 && n < MSG_D) ? W2[k * MSG_D + n] : 0.f;
    g_w2t[i] = f2tf32(v);
}
__global__ void k_prep_ws(const float* __restrict__ W_ih, const float* __restrict__ W_hh) {
    int i = blockIdx.x * blockDim.x + threadIdx.x;
    if (i >= KGRU * WSTK_P) return;
    int k = i / WSTK_P, n = i - k * WSTK_P;
    int g = n / SLAB, c = n - g * SLAB;
    float v = 0.f;
    if (c < MEM_D) {
        if (k < MSG_D)                      v = W_ih[k * 1500 + g * MEM_D + c];
        else if (k >= KB && k < KB + MEM_D) v = W_hh[(k - KB) * 1500 + g * MEM_D + c];
    }
    g_wstk[i] = f2tf32(v);
}

// ---------------- raw build (tf32 raw, tf32 x.h, fp32 h) ----------------
// cos arg is O(1e6): mul and add rounded SEPARATELY (matches XLA), accurate cosf.
__global__ void k_raw(const float* __restrict__ memory,
                      const float* __restrict__ last_update,
                      const float* __restrict__ edge_feats,
                      const float* __restrict__ w_t,
                      const float* __restrict__ b_t,
                      const int*   __restrict__ node_ids,
                      const int*   __restrict__ edge_times) {
    int e = blockIdx.x;
    int n = node_ids[e];
    float dt = __fadd_rn((float)edge_times[e], -last_update[n]);
    const float* mrow = memory + (size_t)n * MEM_D;
    uint32_t* rdst = g_rawt + (size_t)e * RAW_P;
    uint32_t* xdst = g_x    + (size_t)e * KGRU;
    float*    hdst = g_h    + (size_t)e * H_P;
    if (threadIdx.x < 4) {
        xdst[MSG_D + threadIdx.x] = 0u;          // x cols 100..104
        xdst[KB + MEM_D + threadIdx.x] = 0u;     // x cols 604..608
    }
    for (int i = threadIdx.x; i < RAW_P; i += blockDim.x) {
        float v;
        if (i < MEM_D) {
            v = mrow[i];
            hdst[i] = v;
            xdst[KB + i] = f2tf32(v);
        } else if (i < MEM_D + EDGE_F) {
            v = edge_feats[(size_t)e * EDGE_F + (i - MEM_D)];
        } else if (i < RAW_D) {
            int t = i - (MEM_D + EDGE_F);
            float arg = __fadd_rn(__fmul_rn(dt, w_t[t]), b_t[t]);
            v = cosf(arg);
        } else v = 0.f;
        rdst[i] = f2tf32(v);
    }
}

// ================= wide TF32 GEMM: 512 threads, BM=128, BN=128, 4-stage =========
// 16 warps 4m x 4n, warp tile 32x32 (mf2 x nf4). Used for MLP1.
#define AW_U32 4608           // 128*36 A tile
#define WW_U32 4352           // 32*136 W tile
#define WSTG_U32 (AW_U32 + WW_U32)   // 8960 u32 per stage
template<int RELU>
__global__ __launch_bounds__(512, 1)
void k_gemm_w(const uint32_t* __restrict__ A, int lda,
              const uint32_t* __restrict__ W, int ldw,
              const float* __restrict__ bias, int nbias,
              uint32_t* __restrict__ C, int ldc, int nstore,
              int Kpad) {
    extern __shared__ uint32_t sh[];
    const int tid = threadIdx.x;
    const int lane = tid & 31, wid = tid >> 5;
    const int gid = lane >> 2, tig = lane & 3;
    const int wm = wid >> 2, wn = wid & 3;
    const int n0 = blockIdx.x * 128, m0 = blockIdx.y * 128;
    const int KT = Kpad >> 5;
    const uint32_t shb = (uint32_t)__cvta_generic_to_shared(sh);

    float acc[2][4][4];
#pragma unroll
    for (int i = 0; i < 2; i++)
#pragma unroll
        for (int j = 0; j < 4; j++)
#pragma unroll
            for (int c = 0; c < 4; c++) acc[i][j][c] = 0.f;

    auto issue = [&](int kt, int buf) {
        const int k0 = kt << 5;
        uint32_t abase = shb + (uint32_t)(buf * WSTG_U32) * 4u;
        uint32_t wbase = abase + AW_U32 * 4u;
#pragma unroll
        for (int it = 0; it < 2; it++) {       // A: 1024 chunks / 512 thr
            int c = tid + it * 512;
            int m = c >> 3, kq = (c & 7) * 4;
            int gm = m0 + m;
            int ok = (gm < B_EVT) ? 16 : 0;
            int gmc = (gm < B_EVT) ? gm : 0;
            cpa16(abase + (uint32_t)(m * 36 + kq) * 4u,
                  A + (size_t)gmc * lda + k0 + kq, ok);
        }
#pragma unroll
        for (int it = 0; it < 2; it++) {       // W: 1024 chunks / 512 thr
            int c = tid + it * 512;
            int k = c >> 5, nq = (c & 31) * 4;
            cpa16(wbase + (uint32_t)(k * 136 + nq) * 4u,
                  W + (size_t)(k0 + k) * ldw + n0 + nq, 16);
        }
    };

    issue(0, 0); CPA_COMMIT();
    issue(1, 1); CPA_COMMIT();
    issue(2, 2); CPA_COMMIT();

    for (int kt = 0; kt < KT; kt++) {
        CPA_WAIT2();
        __syncthreads();
        if (kt + 3 < KT) issue(kt + 3, (kt + 3) & 3);
        CPA_COMMIT();
        const uint32_t* As = sh + (kt & 3) * WSTG_U32;   // [128][36]
        const uint32_t* Ws = As + AW_U32;                 // [32][136]
#pragma unroll
        for (int s = 0; s < 4; s++) {
            int kb = s * 8;
            uint32_t a[2][4], b[4][2];
#pragma unroll
            for (int mf = 0; mf < 2; mf++) {
                int r0 = wm * 32 + mf * 16 + gid;
                a[mf][0] = As[(r0)     * 36 + kb + tig];
                a[mf][1] = As[(r0 + 8) * 36 + kb + tig];
                a[mf][2] = As[(r0)     * 36 + kb + tig + 4];
                a[mf][3] = As[(r0 + 8) * 36 + kb + tig + 4];
            }
#pragma unroll
            for (int nf = 0; nf < 4; nf++) {
                int c0 = wn * 32 + nf * 8 + gid;
                b[nf][0] = Ws[(kb + tig)     * 136 + c0];
                b[nf][1] = Ws[(kb + tig + 4) * 136 + c0];
            }
#pragma unroll
            for (int mf = 0; mf < 2; mf++)
#pragma unroll
                for (int nf = 0; nf < 4; nf++) mma8(acc[mf][nf], a[mf], b[nf]);
        }
        __syncthreads();
    }

#pragma unroll
    for (int mf = 0; mf < 2; mf++)
#pragma unroll
        for (int nf = 0; nf < 4; nf++)
#pragma unroll
            for (int c = 0; c < 4; c++) {
                int row = m0 + wm * 32 + mf * 16 + gid + ((c & 2) ? 8 : 0);
                int col = n0 + wn * 32 + nf * 8 + tig * 2 + (c & 1);
                if (row < B_EVT && col < nstore) {
                    float v = acc[mf][nf][c] + ((col < nbias) ? bias[col] : 0.f);
                    if (RELU) v = fmaxf(v, 0.f);
                    C[(size_t)row * ldc + col] = f2tf32(v);
                }
            }
}

// ================= narrow TF32 GEMM (256 thr, 3-stage) for MLP2 ==================
#define AS_U32 4608          // 128*36
#define WS_U32 2304          // 32*72
#define STG_U32 (AS_U32 + WS_U32)
template<int RELU>
__global__ __launch_bounds__(256, 2)
void k_gemm_t(const uint32_t* __restrict__ A, int lda,
              const uint32_t* __restrict__ W, int ldw,
              const float* __restrict__ bias, int nbias,
              uint32_t* __restrict__ C, int ldc, int nstore,
              int Kpad) {
    extern __shared__ uint32_t sh[];
    const int tid = threadIdx.x;
    const int lane = tid & 31, wid = tid >> 5;
    const int gid = lane >> 2, tig = lane & 3;
    const int wm = wid >> 1, wn = wid & 1;
    const int n0 = blockIdx.x * 64, m0 = blockIdx.y * 128;
    const int KT = Kpad >> 5;
    const uint32_t shb = (uint32_t)__cvta_generic_to_shared(sh);

    float acc[2][4][4];
#pragma unroll
    for (int i = 0; i < 2; i++)
#pragma unroll
        for (int j = 0; j < 4; j++)
#pragma unroll
            for (int c = 0; c < 4; c++) acc[i][j][c] = 0.f;

    auto issue = [&](int kt, int buf) {
        const int k0 = kt << 5;
        uint32_t abase = shb + (uint32_t)(buf * STG_U32) * 4u;
        uint32_t wbase = abase + AS_U32 * 4u;
#pragma unroll
        for (int it = 0; it < 4; it++) {
            int c = tid + it * 256;
            int m = c >> 3, kq = (c & 7) * 4;
            int gm = m0 + m;
            int ok = (gm < B_EVT) ? 16 : 0;
            int gmc = (gm < B_EVT) ? gm : 0;
            cpa16(abase + (uint32_t)(m * 36 + kq) * 4u,
                  A + (size_t)gmc * lda + k0 + kq, ok);
        }
#pragma unroll
        for (int it = 0; it < 2; it++) {
            int c = tid + it * 256;
            int k = c >> 4, nq = (c & 15) * 4;
            cpa16(wbase + (uint32_t)(k * 72 + nq) * 4u,
                  W + (size_t)(k0 + k) * ldw + n0 + nq, 16);
        }
    };

    issue(0, 0); CPA_COMMIT();
    issue(1, 1); CPA_COMMIT();

    for (int kt = 0; kt < KT; kt++) {
        CPA_WAIT1();
        __syncthreads();
        if (kt + 2 < KT) issue(kt + 2, (kt + 2) % 3);
        CPA_COMMIT();
        const uint32_t* As = sh + (kt % 3) * STG_U32;
        const uint32_t* Ws = As + AS_U32;
#pragma unroll
        for (int s = 0; s < 4; s++) {
            int kb = s * 8;
            uint32_t a[2][4], b[4][2];
#pragma unroll
            for (int mf = 0; mf < 2; mf++) {
                int r0 = wm * 32 + mf * 16 + gid;
                a[mf][0] = As[(r0)     * 36 + kb + tig];
                a[mf][1] = As[(r0 + 8) * 36 + kb + tig];
                a[mf][2] = As[(r0)     * 36 + kb + tig + 4];
                a[mf][3] = As[(r0 + 8) * 36 + kb + tig + 4];
            }
#pragma unroll
            for (int nf = 0; nf < 4; nf++) {
                int c0 = wn * 32 + nf * 8 + gid;
                b[nf][0] = Ws[(kb + tig)     * 72 + c0];
                b[nf][1] = Ws[(kb + tig + 4) * 72 + c0];
            }
#pragma unroll
            for (int mf = 0; mf < 2; mf++)
#pragma unroll
                for (int nf = 0; nf < 4; nf++) mma8(acc[mf][nf], a[mf], b[nf]);
        }
        __syncthreads();
    }

#pragma unroll
    for (int mf = 0; mf < 2; mf++)
#pragma unroll
        for (int nf = 0; nf < 4; nf++)
#pragma unroll
            for (int c = 0; c < 4; c++) {
                int row = m0 + wm * 32 + mf * 16 + gid + ((c & 2) ? 8 : 0);
                int col = n0 + wn * 32 + nf * 8 + tig * 2 + (c & 1);
                if (row < B_EVT && col < nstore) {
                    float v = acc[mf][nf][c] + ((col < nbias) ? bias[col] : 0.f);
                    if (RELU) v = fmaxf(v, 0.f);
                    C[(size_t)row * ldc + col] = f2tf32(v);
                }
            }
}

// ================= fused TF32 GRU: 512 threads, BN=64, 4-stage ===================
// 16 warps 4m x 4n, warp tile 32x16 (mf2 x nf2), 3 gate slabs of 64 cols each.
#define XG_U32 4608           // 128*36
#define WG_U32 2304           // 32*72 per gate
#define GSTG_U32 (XG_U32 + 3 * WG_U32)   // 11520 u32 per stage
__global__ __launch_bounds__(512, 1)
void k_gru_t(const float* __restrict__ b_ih,
             const float* __restrict__ b_hh,
             float* __restrict__ out) {
    extern __shared__ uint32_t sh[];
    const int tid = threadIdx.x;
    const int lane = tid & 31, wid = tid >> 5;
    const int gid = lane >> 2, tig = lane & 3;
    const int wm = wid >> 2, wn = wid & 3;
    const int n0 = blockIdx.x * 64, m0 = blockIdx.y * 128;
    const int KT = KGRU >> 5;   // 19
    const uint32_t shb = (uint32_t)__cvta_generic_to_shared(sh);

    float ar[2][2][4], az[2][2][4], ani[2][2][4], anh[2][2][4];
#pragma unroll
    for (int i = 0; i < 2; i++)
#pragma unroll
        for (int j = 0; j < 2; j++)
#pragma unroll
            for (int c = 0; c < 4; c++) {
                ar[i][j][c] = az[i][j][c] = ani[i][j][c] = anh[i][j][c] = 0.f;
            }

    auto issue = [&](int kt, int buf) {
        const int k0 = kt << 5;
        uint32_t xbase = shb + (uint32_t)(buf * GSTG_U32) * 4u;
        uint32_t wbase = xbase + XG_U32 * 4u;
#pragma unroll
        for (int it = 0; it < 2; it++) {       // X: 1024 chunks / 512 thr
            int c = tid + it * 512;
            int m = c >> 3, kq = (c & 7) * 4;
            int gm = m0 + m;
            int ok = (gm < B_EVT) ? 16 : 0;
            int gmc = (gm < B_EVT) ? gm : 0;
            cpa16(xbase + (uint32_t)(m * 36 + kq) * 4u,
                  g_x + (size_t)gmc * KGRU + k0 + kq, ok);
        }
#pragma unroll
        for (int it = 0; it < 3; it++) {       // W: 3 slabs x 512 chunks
            int c = tid + it * 512;
            int g = c >> 9, r = c & 511;
            int k = r >> 4, nq = (r & 15) * 4;
            cpa16(wbase + (uint32_t)(g * WG_U32 + k * 72 + nq) * 4u,
                  g_wstk + (size_t)(k0 + k) * WSTK_P + g * SLAB + n0 + nq, 16);
        }
    };

    issue(0, 0); CPA_COMMIT();
    issue(1, 1); CPA_COMMIT();
    issue(2, 2); CPA_COMMIT();

    for (int kt = 0; kt < KT; kt++) {
        CPA_WAIT2();
        __syncthreads();
        if (kt + 3 < KT) issue(kt + 3, (kt + 3) & 3);
        CPA_COMMIT();
        const uint32_t* Xs = sh + (kt & 3) * GSTG_U32;   // [128][36]
        const uint32_t* Wg = Xs + XG_U32;                 // [3][32][72]
        const int k0 = kt << 5;
#pragma unroll
        for (int s = 0; s < 4; s++) {
            int kb = s * 8;
            bool ihSide = (k0 + kb) < KB;
            uint32_t a[2][4], br[2][2], bz[2][2], bn[2][2];
#pragma unroll
            for (int mf = 0; mf < 2; mf++) {
                int r0 = wm * 32 + mf * 16 + gid;
                a[mf][0] = Xs[(r0)     * 36 + kb + tig];
                a[mf][1] = Xs[(r0 + 8) * 36 + kb + tig];
                a[mf][2] = Xs[(r0)     * 36 + kb + tig + 4];
                a[mf][3] = Xs[(r0 + 8) * 36 + kb + tig + 4];
            }
#pragma unroll
            for (int nf = 0; nf < 2; nf++) {
                int c0 = wn * 16 + nf * 8 + gid;
                br[nf][0] = Wg[0 * WG_U32 + (kb + tig)     * 72 + c0];
                br[nf][1] = Wg[0 * WG_U32 + (kb + tig + 4) * 72 + c0];
                bz[nf][0] = Wg[1 * WG_U32 + (kb + tig)     * 72 + c0];
                bz[nf][1] = Wg[1 * WG_U32 + (kb + tig + 4) * 72 + c0];
                bn[nf][0] = Wg[2 * WG_U32 + (kb + tig)     * 72 + c0];
                bn[nf][1] = Wg[2 * WG_U32 + (kb + tig + 4) * 72 + c0];
            }
#pragma unroll
            for (int mf = 0; mf < 2; mf++)
#pragma unroll
                for (int nf = 0; nf < 2; nf++) {
                    mma8(ar[mf][nf], a[mf], br[nf]);
                    mma8(az[mf][nf], a[mf], bz[nf]);
                    if (ihSide) mma8(ani[mf][nf], a[mf], bn[nf]);
                    else        mma8(anh[mf][nf], a[mf], bn[nf]);
                }
        }
        __syncthreads();
    }

#pragma unroll
    for (int mf = 0; mf < 2; mf++)
#pragma unroll
        for (int nf = 0; nf < 2; nf++)
#pragma unroll
            for (int c = 0; c < 4; c++) {
                int rm = m0 + wm * 32 + mf * 16 + gid + ((c & 2) ? 8 : 0);
                int cn = n0 + wn * 16 + nf * 8 + tig * 2 + (c & 1);
                if (rm < B_EVT && cn < MEM_D) {
                    float r  = sigmoidf_(ar[mf][nf][c] + b_ih[cn] + b_hh[cn]);
                    float z  = sigmoidf_(az[mf][nf][c] + b_ih[MEM_D + cn] + b_hh[MEM_D + cn]);
                    float nn = tanhf(ani[mf][nf][c] + b_ih[2 * MEM_D + cn] +
                                     r * (anh[mf][nf][c] + b_hh[2 * MEM_D + cn]));
                    float h  = g_h[(size_t)rm * H_P + cn];
                    out[(size_t)rm * MEM_D + cn] = (1.f - z) * nn + z * h;
                }
            }
}

// ---------------- non-winner rows copy the winner's row ----------------
__global__ void k_fixup(const int* __restrict__ node_ids, float* __restrict__ out) {
    int e = blockIdx.x;
    int w = g_winner[node_ids[e]];
    if (w == e) return;
    const float4* src = (const float4*)(out + (size_t)w * MEM_D);
    float4*       dst = (float4*)(out + (size_t)e * MEM_D);
    for (int i = threadIdx.x; i < MEM_D / 4; i += blockDim.x) dst[i] = src[i];
}

// ---------------- launch ----------------
extern "C" void kernel_launch(void* const* d_in, const int* in_sizes, int n_in,
                              void* d_out, int out_size) {
    const float* memory      = (const float*)d_in[0];
    const float* last_update = (const float*)d_in[1];
    const float* edge_feats  = (const float*)d_in[2];
    const float* w_t         = (const float*)d_in[3];
    const float* b_t         = (const float*)d_in[4];
    const float* W1          = (const float*)d_in[5];
    const float* b1          = (const float*)d_in[6];
    const float* W2          = (const float*)d_in[7];
    const float* b2          = (const float*)d_in[8];
    const float* W_ih        = (const float*)d_in[9];
    const float* W_hh        = (const float*)d_in[10];
    const float* b_ih        = (const float*)d_in[11];
    const float* b_hh        = (const float*)d_in[12];
    // d_in[13] default_memory: dead (all output nodes touched, times >= 1)
    const int*   node_ids    = (const int*)d_in[14];
    const int*   edge_times  = (const int*)d_in[15];
    float* out = (float*)d_out;

    static int attr_done = 0;
    const int SM_MLP1 = WSTG_U32 * 4 * 4;   // 143360 B
    const int SM_GEMM = STG_U32 * 3 * 4;    // 82944 B
    const int SM_GRU  = GSTG_U32 * 4 * 4;   // 184320 B
    if (!attr_done) {
        cudaFuncSetAttribute(k_gemm_w<1>, cudaFuncAttributeMaxDynamicSharedMemorySize, SM_MLP1);
        cudaFuncSetAttribute(k_gemm_t<0>, cudaFuncAttributeMaxDynamicSharedMemorySize, SM_GEMM);
        cudaFuncSetAttribute(k_gru_t,     cudaFuncAttributeMaxDynamicSharedMemorySize, SM_GRU);
        attr_done = 1;
    }

    void *winner_p, *rawt_p, *act_p, *x_p, *w1_p, *w2_p;
    cudaGetSymbolAddress(&winner_p, g_winner);
    cudaGetSymbolAddress(&rawt_p,   g_rawt);
    cudaGetSymbolAddress(&act_p,    g_act);
    cudaGetSymbolAddress(&x_p,      g_x);
    cudaGetSymbolAddress(&w1_p,     g_w1t);
    cudaGetSymbolAddress(&w2_p,     g_w2t);

    cudaMemsetAsync(winner_p, 0xFF, sizeof(int) * N_NODES);
    k_winner<<<(B_EVT + 255) / 256, 256>>>(node_ids);
    k_prep_w1<<<(RAW_P * W1_P + 255) / 256, 256>>>(W1);
    k_prep_w2<<<(ACT_P * W2_P + 255) / 256, 256>>>(W2);
    k_prep_ws<<<(KGRU * WSTK_P + 255) / 256, 256>>>(W_ih, W_hh);
    k_raw<<<B_EVT, 128>>>(memory, last_update, edge_feats, w_t, b_t, node_ids, edge_times);

    // MLP1: act(tf32) = relu(raw @ W1 + b1); 3 n-blocks of 128 cover 384 >= 352
    {
        dim3 g(3, MBLK);
        k_gemm_w<1><<<g, 512, SM_MLP1>>>((const uint32_t*)rawt_p, RAW_P,
                                         (const uint32_t*)w1_p, W1_P,
                                         b1, 350,
                                         (uint32_t*)act_p, ACT_P, ACT_P, RAW_P);
    }
    // MLP2: msg(tf32) -> g_x cols [0,100)
    {
        dim3 g(2, MBLK);
        k_gemm_t<0><<<g, 256, SM_GEMM>>>((const uint32_t*)act_p, ACT_P,
                                         (const uint32_t*)w2_p, W2_P,
                                         b2, MSG_D,
                                         (uint32_t*)x_p, KGRU, MSG_D, ACT_P);
    }
    // Fused GRU -> out; 8 n-blocks of 64 cover 512 >= 500
    {
        dim3 g(8, MBLK);
        k_gru_t<<<g, 512, SM_GRU>>>(b_ih, b_hh, out);
    }
    k_fixup<<<B_EVT, 128>>>(node_ids, out);
}

// round 12
// speedup vs baseline: 1.0034x; 1.0034x over previous
#include <cuda_runtime.h>
#include <math.h>
#include <stdint.h>

// ---------------- problem constants ----------------
#define B_EVT   100000
#define N_NODES 500000
#define MEM_D   500
#define MSG_D   100
#define TIME_D  100
#define EDGE_F  101
#define RAW_D   701
#define RAW_P   704          // tf32 raw row stride
#define ACT_P   352          // tf32 act row stride
#define KGRU    608          // [msg(100)|pad4|h(500)|pad4]
#define KB      104          // msg|h boundary (mult of 8)
#define H_P     512          // fp32 h row stride
#define W1_P    384          // w1t col pitch
#define W2_P    128
#define SLAB    512          // wstk per-gate col pitch
#define WSTK_P  1536         // 3*SLAB
#define MBLK    782          // ceil(100000/128)

// ---------------- static scratch ----------------
__device__ __align__(16) int      g_winner[N_NODES];
__device__ __align__(16) uint32_t g_rawt[(size_t)B_EVT * RAW_P];  // tf32 [h|edge|tenc|0]
__device__ __align__(16) uint32_t g_act [(size_t)B_EVT * ACT_P];  // tf32 relu(raw@W1+b1)
__device__ __align__(16) uint32_t g_x   [(size_t)B_EVT * KGRU];   // tf32 [msg|0|h|0]
__device__ __align__(16) float    g_h   [(size_t)B_EVT * H_P];    // fp32 h (epilogue)
__device__ __align__(16) uint32_t g_w1t [(size_t)RAW_P * W1_P];
__device__ __align__(16) uint32_t g_w2t [(size_t)ACT_P * W2_P];
__device__ __align__(16) uint32_t g_wstk[(size_t)KGRU * WSTK_P];

__device__ __forceinline__ float sigmoidf_(float x) { return 1.f / (1.f + expf(-x)); }
__device__ __forceinline__ uint32_t f2tf32(float x) {
    uint32_t r; asm("cvt.rna.tf32.f32 %0, %1;" : "=r"(r) : "f"(x)); return r;
}
__device__ __forceinline__ void mma8(float c[4], const uint32_t a[4], const uint32_t b[2]) {
    asm volatile(
        "mma.sync.aligned.m16n8k8.row.col.f32.tf32.tf32.f32 "
        "{%0,%1,%2,%3},{%4,%5,%6,%7},{%8,%9},{%0,%1,%2,%3};"
        : "+f"(c[0]), "+f"(c[1]), "+f"(c[2]), "+f"(c[3])
        : "r"(a[0]), "r"(a[1]), "r"(a[2]), "r"(a[3]), "r"(b[0]), "r"(b[1]));
}
__device__ __forceinline__ void cpa16(uint32_t dst, const void* src, int nbytes) {
    asm volatile("cp.async.cg.shared.global [%0], [%1], 16, %2;"
                 :: "r"(dst), "l"(src), "r"(nbytes));
}
#define CPA_COMMIT() asm volatile("cp.async.commit_group;")
#define CPA_WAIT1()  asm volatile("cp.async.wait_group 1;")
#define CPA_WAIT2()  asm volatile("cp.async.wait_group 2;")

// ---------------- winner: last event index per node ----------------
__global__ void k_winner(const int* __restrict__ node_ids) {
    int e = blockIdx.x * blockDim.x + threadIdx.x;
    if (e < B_EVT) atomicMax(&g_winner[node_ids[e]], e);
}

// ---------------- weight packing (tf32, zero-padded) ----------------
__global__ void k_prep_w1(const float* __restrict__ W1) {
    int i = blockIdx.x * blockDim.x + threadIdx.x;
    if (i >= RAW_P * W1_P) return;
    int k = i / W1_P, n = i - k * W1_P;
    float v = (k < RAW_D && n < 350) ? W1[k * 350 + n] : 0.f;
    g_w1t[i] = f2tf32(v);
}
__global__ void k_prep_w2(const float* __restrict__ W2) {
    int i = blockIdx.x * blockDim.x + threadIdx.x;
    if (i >= ACT_P * W2_P) return;
    int k = i / W2_P, n = i - k * W2_P;
    float v = (k < 350 && n < MSG_D) ? W2[k * MSG_D + n] : 0.f;
    g_w2t[i] = f2tf32(v);
}
__global__ void k_prep_ws(const float* __restrict__ W_ih, const float* __restrict__ W_hh) {
    int i = blockIdx.x * blockDim.x + threadIdx.x;
    if (i >= KGRU * WSTK_P) return;
    int k = i / WSTK_P, n = i - k * WSTK_P;
    int g = n / SLAB, c = n - g * SLAB;
    float v = 0.f;
    if (c < MEM_D) {
        if (k < MSG_D)                      v = W_ih[k * 1500 + g * MEM_D + c];
        else if (k >= KB && k < KB + MEM_D) v = W_hh[(k - KB) * 1500 + g * MEM_D + c];
    }
    g_wstk[i] = f2tf32(v);
}

// ---------------- raw build (tf32 raw, tf32 x.h, fp32 h) ----------------
// cos arg is O(1e6): mul and add rounded SEPARATELY (matches XLA), accurate cosf.
__global__ void k_raw(const float* __restrict__ memory,
                      const float* __restrict__ last_update,
                      const float* __restrict__ edge_feats,
                      const float* __restrict__ w_t,
                      const float* __restrict__ b_t,
                      const int*   __restrict__ node_ids,
                      const int*   __restrict__ edge_times) {
    int e = blockIdx.x;
    int n = node_ids[e];
    float dt = __fadd_rn((float)edge_times[e], -last_update[n]);
    const float* mrow = memory + (size_t)n * MEM_D;
    uint32_t* rdst = g_rawt + (size_t)e * RAW_P;
    uint32_t* xdst = g_x    + (size_t)e * KGRU;
    float*    hdst = g_h    + (size_t)e * H_P;
    if (threadIdx.x < 4) {
        xdst[MSG_D + threadIdx.x] = 0u;          // x cols 100..104
        xdst[KB + MEM_D + threadIdx.x] = 0u;     // x cols 604..608
    }
    for (int i = threadIdx.x; i < RAW_P; i += blockDim.x) {
        float v;
        if (i < MEM_D) {
            v = mrow[i];
            hdst[i] = v;
            xdst[KB + i] = f2tf32(v);
        } else if (i < MEM_D + EDGE_F) {
            v = edge_feats[(size_t)e * EDGE_F + (i - MEM_D)];
        } else if (i < RAW_D) {
            int t = i - (MEM_D + EDGE_F);
            float arg = __fadd_rn(__fmul_rn(dt, w_t[t]), b_t[t]);
            v = cosf(arg);
        } else v = 0.f;
        rdst[i] = f2tf32(v);
    }
}

// ================= wide TF32 GEMM: 512 threads, BM=128, BN=128, 4-stage =========
// 16 warps 4m x 4n, warp tile 32x32 (mf2 x nf4). Used for MLP1.
#define AW_U32 4608           // 128*36 A tile
#define WW_U32 4352           // 32*136 W tile
#define WSTG_U32 (AW_U32 + WW_U32)   // 8960 u32 per stage
template<int RELU>
__global__ __launch_bounds__(512, 1)
void k_gemm_w(const uint32_t* __restrict__ A, int lda,
              const uint32_t* __restrict__ W, int ldw,
              const float* __restrict__ bias, int nbias,
              uint32_t* __restrict__ C, int ldc, int nstore,
              int Kpad) {
    extern __shared__ uint32_t sh[];
    const int tid = threadIdx.x;
    const int lane = tid & 31, wid = tid >> 5;
    const int gid = lane >> 2, tig = lane & 3;
    const int wm = wid >> 2, wn = wid & 3;
    const int n0 = blockIdx.x * 128, m0 = blockIdx.y * 128;
    const int KT = Kpad >> 5;
    const uint32_t shb = (uint32_t)__cvta_generic_to_shared(sh);

    float acc[2][4][4];
#pragma unroll
    for (int i = 0; i < 2; i++)
#pragma unroll
        for (int j = 0; j < 4; j++)
#pragma unroll
            for (int c = 0; c < 4; c++) acc[i][j][c] = 0.f;

    auto issue = [&](int kt, int buf) {
        const int k0 = kt << 5;
        uint32_t abase = shb + (uint32_t)(buf * WSTG_U32) * 4u;
        uint32_t wbase = abase + AW_U32 * 4u;
#pragma unroll
        for (int it = 0; it < 2; it++) {       // A: 1024 chunks / 512 thr
            int c = tid + it * 512;
            int m = c >> 3, kq = (c & 7) * 4;
            int gm = m0 + m;
            int ok = (gm < B_EVT) ? 16 : 0;
            int gmc = (gm < B_EVT) ? gm : 0;
            cpa16(abase + (uint32_t)(m * 36 + kq) * 4u,
                  A + (size_t)gmc * lda + k0 + kq, ok);
        }
#pragma unroll
        for (int it = 0; it < 2; it++) {       // W: 1024 chunks / 512 thr
            int c = tid + it * 512;
            int k = c >> 5, nq = (c & 31) * 4;
            cpa16(wbase + (uint32_t)(k * 136 + nq) * 4u,
                  W + (size_t)(k0 + k) * ldw + n0 + nq, 16);
        }
    };

    issue(0, 0); CPA_COMMIT();
    issue(1, 1); CPA_COMMIT();
    issue(2, 2); CPA_COMMIT();

    for (int kt = 0; kt < KT; kt++) {
        CPA_WAIT2();
        __syncthreads();
        if (kt + 3 < KT) issue(kt + 3, (kt + 3) & 3);
        CPA_COMMIT();
        const uint32_t* As = sh + (kt & 3) * WSTG_U32;   // [128][36]
        const uint32_t* Ws = As + AW_U32;                 // [32][136]
#pragma unroll
        for (int s = 0; s < 4; s++) {
            int kb = s * 8;
            uint32_t a[2][4], b[4][2];
#pragma unroll
            for (int mf = 0; mf < 2; mf++) {
                int r0 = wm * 32 + mf * 16 + gid;
                a[mf][0] = As[(r0)     * 36 + kb + tig];
                a[mf][1] = As[(r0 + 8) * 36 + kb + tig];
                a[mf][2] = As[(r0)     * 36 + kb + tig + 4];
                a[mf][3] = As[(r0 + 8) * 36 + kb + tig + 4];
            }
#pragma unroll
            for (int nf = 0; nf < 4; nf++) {
                int c0 = wn * 32 + nf * 8 + gid;
                b[nf][0] = Ws[(kb + tig)     * 136 + c0];
                b[nf][1] = Ws[(kb + tig + 4) * 136 + c0];
            }
#pragma unroll
            for (int mf = 0; mf < 2; mf++)
#pragma unroll
                for (int nf = 0; nf < 4; nf++) mma8(acc[mf][nf], a[mf], b[nf]);
        }
        __syncthreads();
    }

#pragma unroll
    for (int mf = 0; mf < 2; mf++)
#pragma unroll
        for (int nf = 0; nf < 4; nf++)
#pragma unroll
            for (int c = 0; c < 4; c++) {
                int row = m0 + wm * 32 + mf * 16 + gid + ((c & 2) ? 8 : 0);
                int col = n0 + wn * 32 + nf * 8 + tig * 2 + (c & 1);
                if (row < B_EVT && col < nstore) {
                    float v = acc[mf][nf][c] + ((col < nbias) ? bias[col] : 0.f);
                    if (RELU) v = fmaxf(v, 0.f);
                    C[(size_t)row * ldc + col] = f2tf32(v);
                }
            }
}

// ================= narrow TF32 GEMM (256 thr, 3-stage) for MLP2 ==================
#define AS_U32 4608          // 128*36
#define WS_U32 2304          // 32*72
#define STG_U32 (AS_U32 + WS_U32)
template<int RELU>
__global__ __launch_bounds__(256, 2)
void k_gemm_t(const uint32_t* __restrict__ A, int lda,
              const uint32_t* __restrict__ W, int ldw,
              const float* __restrict__ bias, int nbias,
              uint32_t* __restrict__ C, int ldc, int nstore,
              int Kpad) {
    extern __shared__ uint32_t sh[];
    const int tid = threadIdx.x;
    const int lane = tid & 31, wid = tid >> 5;
    const int gid = lane >> 2, tig = lane & 3;
    const int wm = wid >> 1, wn = wid & 1;
    const int n0 = blockIdx.x * 64, m0 = blockIdx.y * 128;
    const int KT = Kpad >> 5;
    const uint32_t shb = (uint32_t)__cvta_generic_to_shared(sh);

    float acc[2][4][4];
#pragma unroll
    for (int i = 0; i < 2; i++)
#pragma unroll
        for (int j = 0; j < 4; j++)
#pragma unroll
            for (int c = 0; c < 4; c++) acc[i][j][c] = 0.f;

    auto issue = [&](int kt, int buf) {
        const int k0 = kt << 5;
        uint32_t abase = shb + (uint32_t)(buf * STG_U32) * 4u;
        uint32_t wbase = abase + AS_U32 * 4u;
#pragma unroll
        for (int it = 0; it < 4; it++) {
            int c = tid + it * 256;
            int m = c >> 3, kq = (c & 7) * 4;
            int gm = m0 + m;
            int ok = (gm < B_EVT) ? 16 : 0;
            int gmc = (gm < B_EVT) ? gm : 0;
            cpa16(abase + (uint32_t)(m * 36 + kq) * 4u,
                  A + (size_t)gmc * lda + k0 + kq, ok);
        }
#pragma unroll
        for (int it = 0; it < 2; it++) {
            int c = tid + it * 256;
            int k = c >> 4, nq = (c & 15) * 4;
            cpa16(wbase + (uint32_t)(k * 72 + nq) * 4u,
                  W + (size_t)(k0 + k) * ldw + n0 + nq, 16);
        }
    };

    issue(0, 0); CPA_COMMIT();
    issue(1, 1); CPA_COMMIT();

    for (int kt = 0; kt < KT; kt++) {
        CPA_WAIT1();
        __syncthreads();
        if (kt + 2 < KT) issue(kt + 2, (kt + 2) % 3);
        CPA_COMMIT();
        const uint32_t* As = sh + (kt % 3) * STG_U32;
        const uint32_t* Ws = As + AS_U32;
#pragma unroll
        for (int s = 0; s < 4; s++) {
            int kb = s * 8;
            uint32_t a[2][4], b[4][2];
#pragma unroll
            for (int mf = 0; mf < 2; mf++) {
                int r0 = wm * 32 + mf * 16 + gid;
                a[mf][0] = As[(r0)     * 36 + kb + tig];
                a[mf][1] = As[(r0 + 8) * 36 + kb + tig];
                a[mf][2] = As[(r0)     * 36 + kb + tig + 4];
                a[mf][3] = As[(r0 + 8) * 36 + kb + tig + 4];
            }
#pragma unroll
            for (int nf = 0; nf < 4; nf++) {
                int c0 = wn * 32 + nf * 8 + gid;
                b[nf][0] = Ws[(kb + tig)     * 72 + c0];
                b[nf][1] = Ws[(kb + tig + 4) * 72 + c0];
            }
#pragma unroll
            for (int mf = 0; mf < 2; mf++)
#pragma unroll
                for (int nf = 0; nf < 4; nf++) mma8(acc[mf][nf], a[mf], b[nf]);
        }
        __syncthreads();
    }

#pragma unroll
    for (int mf = 0; mf < 2; mf++)
#pragma unroll
        for (int nf = 0; nf < 4; nf++)
#pragma unroll
            for (int c = 0; c < 4; c++) {
                int row = m0 + wm * 32 + mf * 16 + gid + ((c & 2) ? 8 : 0);
                int col = n0 + wn * 32 + nf * 8 + tig * 2 + (c & 1);
                if (row < B_EVT && col < nstore) {
                    float v = acc[mf][nf][c] + ((col < nbias) ? bias[col] : 0.f);
                    if (RELU) v = fmaxf(v, 0.f);
                    C[(size_t)row * ldc + col] = f2tf32(v);
                }
            }
}

// ================= fused TF32 GRU: 512 threads, BN=64, 4-stage ===================
// 16 warps 4m x 4n, warp tile 32x16 (mf2 x nf2), 3 gate slabs of 64 cols each.
#define XG_U32 4608           // 128*36
#define WG_U32 2304           // 32*72 per gate
#define GSTG_U32 (XG_U32 + 3 * WG_U32)   // 11520 u32 per stage
__global__ __launch_bounds__(512, 1)
void k_gru_t(const float* __restrict__ b_ih,
             const float* __restrict__ b_hh,
             float* __restrict__ out) {
    extern __shared__ uint32_t sh[];
    const int tid = threadIdx.x;
    const int lane = tid & 31, wid = tid >> 5;
    const int gid = lane >> 2, tig = lane & 3;
    const int wm = wid >> 2, wn = wid & 3;
    const int n0 = blockIdx.x * 64, m0 = blockIdx.y * 128;
    const int KT = KGRU >> 5;   // 19
    const uint32_t shb = (uint32_t)__cvta_generic_to_shared(sh);

    float ar[2][2][4], az[2][2][4], ani[2][2][4], anh[2][2][4];
#pragma unroll
    for (int i = 0; i < 2; i++)
#pragma unroll
        for (int j = 0; j < 2; j++)
#pragma unroll
            for (int c = 0; c < 4; c++) {
                ar[i][j][c] = az[i][j][c] = ani[i][j][c] = anh[i][j][c] = 0.f;
            }

    auto issue = [&](int kt, int buf) {
        const int k0 = kt << 5;
        uint32_t xbase = shb + (uint32_t)(buf * GSTG_U32) * 4u;
        uint32_t wbase = xbase + XG_U32 * 4u;
#pragma unroll
        for (int it = 0; it < 2; it++) {       // X: 1024 chunks / 512 thr
            int c = tid + it * 512;
            int m = c >> 3, kq = (c & 7) * 4;
            int gm = m0 + m;
            int ok = (gm < B_EVT) ? 16 : 0;
            int gmc = (gm < B_EVT) ? gm : 0;
            cpa16(xbase + (uint32_t)(m * 36 + kq) * 4u,
                  g_x + (size_t)gmc * KGRU + k0 + kq, ok);
        }
#pragma unroll
        for (int it = 0; it < 3; it++) {       // W: 3 slabs x 512 chunks
            int c = tid + it * 512;
            int g = c >> 9, r = c & 511;
            int k = r >> 4, nq = (r & 15) * 4;
            cpa16(wbase + (uint32_t)(g * WG_U32 + k * 72 + nq) * 4u,
                  g_wstk + (size_t)(k0 + k) * WSTK_P + g * SLAB + n0 + nq, 16);
        }
    };

    issue(0, 0); CPA_COMMIT();
    issue(1, 1); CPA_COMMIT();
    issue(2, 2); CPA_COMMIT();

    for (int kt = 0; kt < KT; kt++) {
        CPA_WAIT2();
        __syncthreads();
        if (kt + 3 < KT) issue(kt + 3, (kt + 3) & 3);
        CPA_COMMIT();
        const uint32_t* Xs = sh + (kt & 3) * GSTG_U32;   // [128][36]
        const uint32_t* Wg = Xs + XG_U32;                 // [3][32][72]
        const int k0 = kt << 5;
#pragma unroll
        for (int s = 0; s < 4; s++) {
            int kb = s * 8;
            bool ihSide = (k0 + kb) < KB;
            uint32_t a[2][4], br[2][2], bz[2][2], bn[2][2];
#pragma unroll
            for (int mf = 0; mf < 2; mf++) {
                int r0 = wm * 32 + mf * 16 + gid;
                a[mf][0] = Xs[(r0)     * 36 + kb + tig];
                a[mf][1] = Xs[(r0 + 8) * 36 + kb + tig];
                a[mf][2] = Xs[(r0)     * 36 + kb + tig + 4];
                a[mf][3] = Xs[(r0 + 8) * 36 + kb + tig + 4];
            }
#pragma unroll
            for (int nf = 0; nf < 2; nf++) {
                int c0 = wn * 16 + nf * 8 + gid;
                br[nf][0] = Wg[0 * WG_U32 + (kb + tig)     * 72 + c0];
                br[nf][1] = Wg[0 * WG_U32 + (kb + tig + 4) * 72 + c0];
                bz[nf][0] = Wg[1 * WG_U32 + (kb + tig)     * 72 + c0];
                bz[nf][1] = Wg[1 * WG_U32 + (kb + tig + 4) * 72 + c0];
                bn[nf][0] = Wg[2 * WG_U32 + (kb + tig)     * 72 + c0];
                bn[nf][1] = Wg[2 * WG_U32 + (kb + tig + 4) * 72 + c0];
            }
#pragma unroll
            for (int mf = 0; mf < 2; mf++)
#pragma unroll
                for (int nf = 0; nf < 2; nf++) {
                    mma8(ar[mf][nf], a[mf], br[nf]);
                    mma8(az[mf][nf], a[mf], bz[nf]);
                    if (ihSide) mma8(ani[mf][nf], a[mf], bn[nf]);
                    else        mma8(anh[mf][nf], a[mf], bn[nf]);
                }
        }
        __syncthreads();
    }

#pragma unroll
    for (int mf = 0; mf < 2; mf++)
#pragma unroll
        for (int nf = 0; nf < 2; nf++)
#pragma unroll
            for (int c = 0; c < 4; c++) {
                int rm = m0 + wm * 32 + mf * 16 + gid + ((c & 2) ? 8 : 0);
                int cn = n0 + wn * 16 + nf * 8 + tig * 2 + (c & 1);
                if (rm < B_EVT && cn < MEM_D) {
                    float r  = sigmoidf_(ar[mf][nf][c] + b_ih[cn] + b_hh[cn]);
                    float z  = sigmoidf_(az[mf][nf][c] + b_ih[MEM_D + cn] + b_hh[MEM_D + cn]);
                    float nn = tanhf(ani[mf][nf][c] + b_ih[2 * MEM_D + cn] +
                                     r * (anh[mf][nf][c] + b_hh[2 * MEM_D + cn]));
                    float h  = g_h[(size_t)rm * H_P + cn];
                    out[(size_t)rm * MEM_D + cn] = (1.f - z) * nn + z * h;
                }
            }
}

// ---------------- non-winner rows copy the winner's row ----------------
__global__ void k_fixup(const int* __restrict__ node_ids, float* __restrict__ out) {
    int e = blockIdx.x;
    int w = g_winner[node_ids[e]];
    if (w == e) return;
    const float4* src = (const float4*)(out + (size_t)w * MEM_D);
    float4*       dst = (float4*)(out + (size_t)e * MEM_D);
    for (int i = threadIdx.x; i < MEM_D / 4; i += blockDim.x) dst[i] = src[i];
}

// ---------------- launch ----------------
extern "C" void kernel_launch(void* const* d_in, const int* in_sizes, int n_in,
                              void* d_out, int out_size) {
    const float* memory      = (const float*)d_in[0];
    const float* last_update = (const float*)d_in[1];
    const float* edge_feats  = (const float*)d_in[2];
    const float* w_t         = (const float*)d_in[3];
    const float* b_t         = (const float*)d_in[4];
    const float* W1          = (const float*)d_in[5];
    const float* b1          = (const float*)d_in[6];
    const float* W2          = (const float*)d_in[7];
    const float* b2          = (const float*)d_in[8];
    const float* W_ih        = (const float*)d_in[9];
    const float* W_hh        = (const float*)d_in[10];
    const float* b_ih        = (const float*)d_in[11];
    const float* b_hh        = (const float*)d_in[12];
    // d_in[13] default_memory: dead (all output nodes touched, times >= 1)
    const int*   node_ids    = (const int*)d_in[14];
    const int*   edge_times  = (const int*)d_in[15];
    float* out = (float*)d_out;

    static int attr_done = 0;
    const int SM_MLP1 = WSTG_U32 * 4 * 4;   // 143360 B
    const int SM_GEMM = STG_U32 * 3 * 4;    // 82944 B
    const int SM_GRU  = GSTG_U32 * 4 * 4;   // 184320 B
    if (!attr_done) {
        cudaFuncSetAttribute(k_gemm_w<1>, cudaFuncAttributeMaxDynamicSharedMemorySize, SM_MLP1);
        cudaFuncSetAttribute(k_gemm_t<0>, cudaFuncAttributeMaxDynamicSharedMemorySize, SM_GEMM);
        cudaFuncSetAttribute(k_gru_t,     cudaFuncAttributeMaxDynamicSharedMemorySize, SM_GRU);
        attr_done = 1;
    }

    void *winner_p, *rawt_p, *act_p, *x_p, *w1_p, *w2_p;
    cudaGetSymbolAddress(&winner_p, g_winner);
    cudaGetSymbolAddress(&rawt_p,   g_rawt);
    cudaGetSymbolAddress(&act_p,    g_act);
    cudaGetSymbolAddress(&x_p,      g_x);
    cudaGetSymbolAddress(&w1_p,     g_w1t);
    cudaGetSymbolAddress(&w2_p,     g_w2t);

    cudaMemsetAsync(winner_p, 0xFF, sizeof(int) * N_NODES);
    k_winner<<<(B_EVT + 255) / 256, 256>>>(node_ids);
    k_prep_w1<<<(RAW_P * W1_P + 255) / 256, 256>>>(W1);
    k_prep_w2<<<(ACT_P * W2_P + 255) / 256, 256>>>(W2);
    k_prep_ws<<<(KGRU * WSTK_P + 255) / 256, 256>>>(W_ih, W_hh);
    k_raw<<<B_EVT, 128>>>(memory, last_update, edge_feats, w_t, b_t, node_ids, edge_times);

    // MLP1: act(tf32) = relu(raw @ W1 + b1); 3 n-blocks of 128 cover 384 >= 352
    {
        dim3 g(3, MBLK);
        k_gemm_w<1><<<g, 512, SM_MLP1>>>((const uint32_t*)rawt_p, RAW_P,
                                         (const uint32_t*)w1_p, W1_P,
                                         b1, 350,
                                         (uint32_t*)act_p, ACT_P, ACT_P, RAW_P);
    }
    // MLP2: msg(tf32) -> g_x cols [0,100)
    {
        dim3 g(2, MBLK);
        k_gemm_t<0><<<g, 256, SM_GEMM>>>((const uint32_t*)act_p, ACT_P,
                                         (const uint32_t*)w2_p, W2_P,
                                         b2, MSG_D,
                                         (uint32_t*)x_p, KGRU, MSG_D, ACT_P);
    }
    // Fused GRU -> out; 8 n-blocks of 64 cover 512 >= 500
    {
        dim3 g(8, MBLK);
        k_gru_t<<<g, 512, SM_GRU>>>(b_ih, b_hh, out);
    }
    k_fixup<<<B_EVT, 128>>>(node_ids, out);
}